// round 6
// baseline (speedup 1.0000x reference)
#include <cuda_runtime.h>
#include <cuda_bf16.h>
#include <math.h>
#include <stdint.h>

#define BB 256
#define NN 256
#define DD 136
#define HH 128
#define ROWS (BB*NN)

#define K1PAD 152      // layer-1 K stride (304B rows -> conflict-free ldmatrix)
#define K2PAD 136      // layer-2 W stride (272B rows -> conflict-free)
#define NT    256      // 8 warps, each 16 rows x 128 cols

__device__ float g_scores[ROWS];

// ---------------- smem layout ----------------
#define A_BYTES  (128 * K1PAD * 2)          // 38912
#define W2_BYTES (128 * K2PAD * 2)          // 34816
#define OFF_AH   0
#define OFF_AL   (A_BYTES)
#define OFF_W1H  (2 * A_BYTES)
#define OFF_W1L  (3 * A_BYTES)
#define OFF_W2H  (4 * A_BYTES)
#define OFF_W2L  (OFF_W2H + W2_BYTES)
#define OFF_B1   (OFF_W2L + W2_BYTES)       // 225280
#define OFF_B2   (OFF_B1 + 512)
#define OFF_W3   (OFF_B2 + 512)
#define SMEM_BYTES (OFF_W3 + 512)           // 226816

__device__ __forceinline__ uint32_t smem_u32(const void* p) {
    uint32_t a;
    asm("{ .reg .u64 t; cvta.to.shared.u64 t, %1; cvt.u32.u64 %0, t; }" : "=r"(a) : "l"(p));
    return a;
}
__device__ __forceinline__ void ldsm_x4(uint32_t* r, uint32_t addr) {
    asm volatile("ldmatrix.sync.aligned.m8n8.x4.shared.b16 {%0,%1,%2,%3}, [%4];"
        : "=r"(r[0]), "=r"(r[1]), "=r"(r[2]), "=r"(r[3]) : "r"(addr));
}
__device__ __forceinline__ void mma16816(float* d, const uint32_t* a, uint32_t b0, uint32_t b1) {
    asm volatile("mma.sync.aligned.m16n8k16.row.col.f32.bf16.bf16.f32 "
        "{%0,%1,%2,%3}, {%4,%5,%6,%7}, {%8,%9}, {%0,%1,%2,%3};"
        : "+f"(d[0]), "+f"(d[1]), "+f"(d[2]), "+f"(d[3])
        : "r"(a[0]), "r"(a[1]), "r"(a[2]), "r"(a[3]), "r"(b0), "r"(b1));
}
__device__ __forceinline__ uint32_t pack_hi(float x, float y) {
    __nv_bfloat16 h0 = __float2bfloat16(x), h1 = __float2bfloat16(y);
    return ((uint32_t)__bfloat16_as_ushort(h1) << 16) | __bfloat16_as_ushort(h0);
}
__device__ __forceinline__ uint32_t pack_lo(float x, float y) {
    __nv_bfloat16 h0 = __float2bfloat16(x), h1 = __float2bfloat16(y);
    __nv_bfloat16 l0 = __float2bfloat16(x - __bfloat162float(h0));
    __nv_bfloat16 l1 = __float2bfloat16(y - __bfloat162float(h1));
    return ((uint32_t)__bfloat16_as_ushort(l1) << 16) | __bfloat16_as_ushort(l0);
}

// ---------------- fused MLP: staging + 2 MMA layers, no mid-kernel syncs ----------------
__global__ __launch_bounds__(NT, 1)
void mlp_mma(const float* __restrict__ feat,
             const float* __restrict__ W1, const float* __restrict__ b1,
             const float* __restrict__ W2, const float* __restrict__ b2,
             const float* __restrict__ W3, const float* __restrict__ b3)
{
    extern __shared__ char smem[];
    __nv_bfloat16* AH = (__nv_bfloat16*)(smem + OFF_AH);
    __nv_bfloat16* AL = (__nv_bfloat16*)(smem + OFF_AL);
    __nv_bfloat16* W1H = (__nv_bfloat16*)(smem + OFF_W1H);
    __nv_bfloat16* W1L = (__nv_bfloat16*)(smem + OFF_W1L);
    __nv_bfloat16* W2H = (__nv_bfloat16*)(smem + OFF_W2H);
    __nv_bfloat16* W2L = (__nv_bfloat16*)(smem + OFF_W2L);
    float* sB1 = (float*)(smem + OFF_B1);
    float* sB2 = (float*)(smem + OFF_B2);
    float* sW3 = (float*)(smem + OFF_W3);

    const int tid  = threadIdx.x;
    const int lane = tid & 31;
    const int wid  = tid >> 5;
    const int m0   = wid * 16;
    const long row0 = (long)blockIdx.x * 128;

    const uint32_t uAH  = smem_u32(AH);
    const uint32_t uAL  = smem_u32(AL);
    const uint32_t uW1H = smem_u32(W1H);
    const uint32_t uW1L = smem_u32(W1L);
    const uint32_t uW2H = smem_u32(W2H);
    const uint32_t uW2L = smem_u32(W2L);

    // ldmatrix address components (unchanged from validated R4/R5 layout)
    const int a_row = m0 + (lane & 7) + ((lane >> 3) & 1) * 8;
    const int a_kof = (lane >> 4) * 8;
    const int w_rof = (lane & 7) + (lane >> 4) * 8;
    const int w_kof = ((lane >> 3) & 1) * 8;

    // ---- stage biases / W3 ----
    if (tid < 128) { sB1[tid] = b1[tid]; sB2[tid] = b2[tid]; sW3[tid] = W3[tid]; }
    const float b3v = __ldg(b3);

    // ---- stage features: row r = tid>>1, half h = tid&1 (34 pairs each) ----
    {
        const int r = tid >> 1, h = tid & 1;
        const float2* fb = (const float2*)(feat + (row0 + r) * DD) + 34 * h;
        #pragma unroll
        for (int half = 0; half < 2; half++) {
            float2 v[17];
            #pragma unroll
            for (int t = 0; t < 17; t++) v[t] = fb[17 * half + t];
            #pragma unroll
            for (int t = 0; t < 17; t++) {
                const int p = 34 * h + 17 * half + t;    // pair index, k = 2p
                *(uint32_t*)(AH + r * K1PAD + 2 * p) = pack_hi(v[t].x, v[t].y);
                *(uint32_t*)(AL + r * K1PAD + 2 * p) = pack_lo(v[t].x, v[t].y);
            }
        }
        // zero pad pairs 68..75 (k = 136..151)
        #pragma unroll
        for (int q = 0; q < 4; q++) {
            const int p = 68 + 4 * h + q;
            *(uint32_t*)(AH + r * K1PAD + 2 * p) = 0;
            *(uint32_t*)(AL + r * K1PAD + 2 * p) = 0;
        }
    }

    // ---- stage W1: split + transpose [k][n] -> [n][k], coalesced reads ----
    #pragma unroll 4
    for (int q = tid; q < 136 * 32; q += NT) {
        const int k = q >> 5, n4 = (q & 31) * 4;
        float4 w = *(const float4*)(W1 + k * HH + n4);
        const float* we = (const float*)&w;
        #pragma unroll
        for (int e = 0; e < 4; e++) {
            const int n = n4 + e;
            __nv_bfloat16 hi = __float2bfloat16(we[e]);
            __nv_bfloat16 lo = __float2bfloat16(we[e] - __bfloat162float(hi));
            W1H[n * K1PAD + k] = hi;
            W1L[n * K1PAD + k] = lo;
        }
    }
    // zero-fill W1 rows k = 136..151
    for (int q = tid; q < 1024; q += NT) {
        const int n = q >> 3, pp = q & 7;
        *(uint32_t*)(W1H + n * K1PAD + 136 + 2 * pp) = 0;
        *(uint32_t*)(W1L + n * K1PAD + 136 + 2 * pp) = 0;
    }
    // ---- stage W2 ----
    #pragma unroll 4
    for (int q = tid; q < 128 * 32; q += NT) {
        const int k = q >> 5, n4 = (q & 31) * 4;
        float4 w = *(const float4*)(W2 + k * HH + n4);
        const float* we = (const float*)&w;
        #pragma unroll
        for (int e = 0; e < 4; e++) {
            const int n = n4 + e;
            __nv_bfloat16 hi = __float2bfloat16(we[e]);
            __nv_bfloat16 lo = __float2bfloat16(we[e] - __bfloat162float(hi));
            W2H[n * K2PAD + k] = hi;
            W2L[n * K2PAD + k] = lo;
        }
    }
    __syncthreads();   // the only block-wide sync

    // ================= layer 1: 16x128 per warp, 9 ksteps =================
    float acc[16][4];
    #pragma unroll
    for (int t = 0; t < 16; t++)
        #pragma unroll
        for (int q = 0; q < 4; q++) acc[t][q] = 0.f;

    #pragma unroll
    for (int ks = 0; ks < 9; ks++) {
        const int k0 = ks * 16;
        uint32_t ah[4], al[4];
        ldsm_x4(ah, uAH + (a_row * K1PAD + k0 + a_kof) * 2);
        ldsm_x4(al, uAL + (a_row * K1PAD + k0 + a_kof) * 2);
        #pragma unroll
        for (int np = 0; np < 8; np++) {
            const int n0 = np * 16;
            uint32_t wh[4], wl[4];
            ldsm_x4(wh, uW1H + ((n0 + w_rof) * K1PAD + k0 + w_kof) * 2);
            ldsm_x4(wl, uW1L + ((n0 + w_rof) * K1PAD + k0 + w_kof) * 2);
            mma16816(acc[2*np],   ah, wh[0], wh[1]);
            mma16816(acc[2*np],   ah, wl[0], wl[1]);
            mma16816(acc[2*np],   al, wh[0], wh[1]);
            mma16816(acc[2*np+1], ah, wh[2], wh[3]);
            mma16816(acc[2*np+1], ah, wl[2], wl[3]);
            mma16816(acc[2*np+1], al, wh[2], wh[3]);
        }
    }

    // ===== epilogue 1 (in registers): relu(+b1) -> layer-2 A fragments =====
    // accumulator frag (rows r,r+8 / cols 2c,2c+1 of each n8 tile) == A-operand frag
    uint32_t A2h[8][4], A2l[8][4];
    {
        const int c = 2 * (lane & 3);
        #pragma unroll
        for (int ks = 0; ks < 8; ks++) {
            const int c0 = 16 * ks + c;       // cols for a0/a1
            const int c1 = c0 + 8;            // cols for a2/a3
            float v00 = fmaxf(acc[2*ks][0]   + sB1[c0],     0.f);
            float v01 = fmaxf(acc[2*ks][1]   + sB1[c0 + 1], 0.f);
            float v02 = fmaxf(acc[2*ks][2]   + sB1[c0],     0.f);
            float v03 = fmaxf(acc[2*ks][3]   + sB1[c0 + 1], 0.f);
            float v10 = fmaxf(acc[2*ks+1][0] + sB1[c1],     0.f);
            float v11 = fmaxf(acc[2*ks+1][1] + sB1[c1 + 1], 0.f);
            float v12 = fmaxf(acc[2*ks+1][2] + sB1[c1],     0.f);
            float v13 = fmaxf(acc[2*ks+1][3] + sB1[c1 + 1], 0.f);
            A2h[ks][0] = pack_hi(v00, v01);  A2l[ks][0] = pack_lo(v00, v01);
            A2h[ks][1] = pack_hi(v02, v03);  A2l[ks][1] = pack_lo(v02, v03);
            A2h[ks][2] = pack_hi(v10, v11);  A2l[ks][2] = pack_lo(v10, v11);
            A2h[ks][3] = pack_hi(v12, v13);  A2l[ks][3] = pack_lo(v12, v13);
        }
    }

    // ================= layer 2: A from registers, 8 ksteps =================
    #pragma unroll
    for (int t = 0; t < 16; t++)
        #pragma unroll
        for (int q = 0; q < 4; q++) acc[t][q] = 0.f;

    #pragma unroll
    for (int ks = 0; ks < 8; ks++) {
        const int k0 = ks * 16;
        #pragma unroll
        for (int np = 0; np < 8; np++) {
            const int n0 = np * 16;
            uint32_t wh[4], wl[4];
            ldsm_x4(wh, uW2H + ((n0 + w_rof) * K2PAD + k0 + w_kof) * 2);
            ldsm_x4(wl, uW2L + ((n0 + w_rof) * K2PAD + k0 + w_kof) * 2);
            mma16816(acc[2*np],   A2h[ks], wh[0], wh[1]);
            mma16816(acc[2*np],   A2h[ks], wl[0], wl[1]);
            mma16816(acc[2*np],   A2l[ks], wh[0], wh[1]);
            mma16816(acc[2*np+1], A2h[ks], wh[2], wh[3]);
            mma16816(acc[2*np+1], A2h[ks], wl[2], wl[3]);
            mma16816(acc[2*np+1], A2l[ks], wh[2], wh[3]);
        }
    }

    // ===== epilogue 2: relu(+b2) . W3, shfl reduce, direct score write =====
    {
        float pl = 0.f, ph = 0.f;
        const int c4 = 2 * (lane & 3);
        #pragma unroll
        for (int nt = 0; nt < 16; nt++) {
            const int cc = 8 * nt + c4;
            pl = fmaf(fmaxf(acc[nt][0] + sB2[cc],     0.f), sW3[cc],     pl);
            pl = fmaf(fmaxf(acc[nt][1] + sB2[cc + 1], 0.f), sW3[cc + 1], pl);
            ph = fmaf(fmaxf(acc[nt][2] + sB2[cc],     0.f), sW3[cc],     ph);
            ph = fmaf(fmaxf(acc[nt][3] + sB2[cc + 1], 0.f), sW3[cc + 1], ph);
        }
        pl += __shfl_xor_sync(0xFFFFFFFF, pl, 1);
        pl += __shfl_xor_sync(0xFFFFFFFF, pl, 2);
        ph += __shfl_xor_sync(0xFFFFFFFF, ph, 1);
        ph += __shfl_xor_sync(0xFFFFFFFF, ph, 2);
        if ((lane & 3) == 0) {
            const int r = m0 + (lane >> 2);
            g_scores[row0 + r]     = pl + b3v;
            g_scores[row0 + r + 8] = ph + b3v;
        }
    }
}

// ---------------- pairwise lambda kernel: 2 blocks per batch ----------------
__global__ __launch_bounds__(128, 8)
void lambda_kernel(const int* __restrict__ labels, float* __restrict__ out)
{
    __shared__ float4 elg[NN];     // {exp(s), 1+log2(1+s), 2^label, 0}

    const int bid   = blockIdx.x;
    const int batch = bid >> 1;
    const int half  = bid & 1;
    const int tid   = threadIdx.x;

    for (int j = tid; j < NN; j += 128) {
        float s = g_scores[batch * NN + j];
        int   l = labels[batch * NN + j];
        elg[j] = make_float4(expf(s), 1.0f + log2f(1.0f + s), exp2f((float)l), 0.f);
    }
    __syncthreads();

    const int i = half * 128 + tid;
    const float4 me = elg[i];
    const float ei = me.x, Mi = me.y, gi = me.z;

    float acc = 0.f;
    #pragma unroll 8
    for (int j = 0; j < NN; j++) {
        float4 v  = elg[j];
        float sg  = gi - v.z;                 // sign(li-lj)
        float t   = (sg > 0.f) ? ei : v.x;
        float num = sg * t;
        float den = fabsf(fmaxf(Mi, v.y)) * (ei + v.x);
        acc += __fdividef(num, den);
    }
    out[batch * NN + i] = 0.5f * acc;
}

extern "C" void kernel_launch(void* const* d_in, const int* in_sizes, int n_in,
                              void* d_out, int out_size)
{
    const float* feat   = (const float*)d_in[0];
    const int*   labels = (const int*)d_in[1];
    const float* W1 = (const float*)d_in[2];
    const float* b1 = (const float*)d_in[3];
    const float* W2 = (const float*)d_in[4];
    const float* b2 = (const float*)d_in[5];
    const float* W3 = (const float*)d_in[6];
    const float* b3 = (const float*)d_in[7];
    float* out = (float*)d_out;

    static bool attr_set = false;
    if (!attr_set) {
        cudaFuncSetAttribute(mlp_mma, cudaFuncAttributeMaxDynamicSharedMemorySize,
                             (int)SMEM_BYTES);
        attr_set = true;
    }

    mlp_mma<<<ROWS / 128, NT, SMEM_BYTES>>>(feat, W1, b1, W2, b2, W3, b3);
    lambda_kernel<<<2 * BB, 128>>>(labels, out);
}

// round 7
// speedup vs baseline: 2.6897x; 2.6897x over previous
#include <cuda_runtime.h>
#include <cuda_fp16.h>
#include <math.h>
#include <stdint.h>

#define BB 256
#define NN 256
#define DD 136
#define HH 128
#define ROWS (BB*NN)

#define K1PAD 152      // layer-1 K stride (304B rows -> conflict-free ldmatrix)
#define K2PAD 136      // layer-2 K stride (272B rows -> conflict-free)
#define NT    512      // 16 warps

// ---------------- scratch globals ----------------
__device__ float g_scores[ROWS];
__device__ __align__(16) __half g_W1t[HH * K1PAD];   // fp16, transposed [n][k], zero-padded
__device__ __align__(16) __half g_W2t[HH * K2PAD];

// ---------------- smem layout (everything staged once) ----------------
#define A_BYTES  (128 * K1PAD * 2)          // 38912
#define W1_BYTES (128 * K1PAD * 2)          // 38912
#define W2_BYTES (128 * K2PAD * 2)          // 34816
#define OFF_AH   0
#define OFF_AL   (A_BYTES)                  // 38912
#define OFF_W1   (2 * A_BYTES)              // 77824
#define OFF_W2   (OFF_W1 + W1_BYTES)        // 116736
#define OFF_B1   (OFF_W2 + W2_BYTES)        // 151552
#define OFF_B2   (OFF_B1 + 512)
#define OFF_W3   (OFF_B2 + 512)
#define OFF_RED  (OFF_W3 + 512)
#define SMEM_BYTES (OFF_RED + 1024)         // 154112

__device__ __forceinline__ uint32_t smem_u32(const void* p) {
    uint32_t a;
    asm("{ .reg .u64 t; cvta.to.shared.u64 t, %1; cvt.u32.u64 %0, t; }" : "=r"(a) : "l"(p));
    return a;
}
__device__ __forceinline__ void cp_async16(uint32_t dst, const void* src) {
    asm volatile("cp.async.cg.shared.global [%0], [%1], 16;" :: "r"(dst), "l"(src));
}
#define CP_COMMIT() asm volatile("cp.async.commit_group;" ::: "memory")
#define CP_WAIT0()  asm volatile("cp.async.wait_group 0;" ::: "memory")

__device__ __forceinline__ void ldsm_x4(uint32_t* r, uint32_t addr) {
    asm volatile("ldmatrix.sync.aligned.m8n8.x4.shared.b16 {%0,%1,%2,%3}, [%4];"
        : "=r"(r[0]), "=r"(r[1]), "=r"(r[2]), "=r"(r[3]) : "r"(addr));
}
__device__ __forceinline__ void mma16816(float* d, const uint32_t* a, uint32_t b0, uint32_t b1) {
    asm volatile("mma.sync.aligned.m16n8k16.row.col.f32.f16.f16.f32 "
        "{%0,%1,%2,%3}, {%4,%5,%6,%7}, {%8,%9}, {%0,%1,%2,%3};"
        : "+f"(d[0]), "+f"(d[1]), "+f"(d[2]), "+f"(d[3])
        : "r"(a[0]), "r"(a[1]), "r"(a[2]), "r"(a[3]), "r"(b0), "r"(b1));
}
__device__ __forceinline__ uint32_t pack_hi(float x, float y) {
    __half h0 = __float2half_rn(x), h1 = __float2half_rn(y);
    return ((uint32_t)__half_as_ushort(h1) << 16) | __half_as_ushort(h0);
}
__device__ __forceinline__ uint32_t pack_lo(float x, float y) {
    __half h0 = __float2half_rn(x), h1 = __float2half_rn(y);
    __half l0 = __float2half_rn(x - __half2float(h0));
    __half l1 = __float2half_rn(y - __half2float(h1));
    return ((uint32_t)__half_as_ushort(l1) << 16) | __half_as_ushort(l0);
}

// ---------------- weight prep: fp16 round + transpose to [n][k] ----------------
__global__ void prep_w(const float* __restrict__ W1, const float* __restrict__ W2) {
    int idx = blockIdx.x * 256 + threadIdx.x;
    if (idx < HH * K1PAD) {
        int n = idx & 127, k = idx >> 7;     // coalesced read of W1[k*128+n]
        float v = (k < DD) ? W1[k * HH + n] : 0.f;
        g_W1t[n * K1PAD + k] = __float2half_rn(v);
        return;
    }
    int idx2 = idx - HH * K1PAD;
    if (idx2 < HH * 128) {
        int n = idx2 & 127, k = idx2 >> 7;
        g_W2t[n * K2PAD + k] = __float2half_rn(W2[k * HH + n]);
    }
}

// ---------------- fused MLP, warp-level fp16 MMA (A split hi/lo) ----------------
__global__ __launch_bounds__(NT, 1)
void mlp_mma(const float* __restrict__ feat,
             const float* __restrict__ b1, const float* __restrict__ b2,
             const float* __restrict__ W3, const float* __restrict__ b3)
{
    extern __shared__ char smem[];
    __half* AH = (__half*)(smem + OFF_AH);
    __half* AL = (__half*)(smem + OFF_AL);
    float* sB1 = (float*)(smem + OFF_B1);
    float* sB2 = (float*)(smem + OFF_B2);
    float* sW3 = (float*)(smem + OFF_W3);
    float* red = (float*)(smem + OFF_RED);

    const int tid  = threadIdx.x;
    const int lane = tid & 31;
    const int wid  = tid >> 5;
    const int m0    = (wid >> 1) * 16;
    const int nside = (wid & 1) * 64;
    const long row0 = (long)blockIdx.x * 128;

    const uint32_t uAH = smem_u32(smem + OFF_AH);
    const uint32_t uAL = smem_u32(smem + OFF_AL);
    const uint32_t uW1 = smem_u32(smem + OFF_W1);
    const uint32_t uW2 = smem_u32(smem + OFF_W2);

    // ldmatrix address components
    const int a_row = m0 + (lane & 7) + ((lane >> 3) & 1) * 8;
    const int a_kof = (lane >> 4) * 8;
    const int w_rof = (lane & 7) + (lane >> 4) * 8;
    const int w_kof = ((lane >> 3) & 1) * 8;

    // ---- stage 1: weight tiles via cp.async ----
    {
        const char* s;
        s = (const char*)g_W1t;
        for (int i = tid; i < W1_BYTES / 16; i += NT) cp_async16(uW1 + i * 16, s + i * 16);
        s = (const char*)g_W2t;
        for (int i = tid; i < W2_BYTES / 16; i += NT) cp_async16(uW2 + i * 16, s + i * 16);
        CP_COMMIT();
    }

    // ---- stage 2: biases / W3 ----
    if (tid < 128) { sB1[tid] = b1[tid]; sB2[tid] = b2[tid]; sW3[tid] = W3[tid]; }

    // ---- stage 3: features, batched loads then convert/store ----
    {
        const int r  = tid >> 2;        // row 0..127
        const int c4 = tid & 3;         // pair-lane
        const float* fb = feat + row0 * DD + (long)r * DD + 2 * c4;
        float2 v[17];
        #pragma unroll
        for (int it = 0; it < 17; it++) v[it] = *(const float2*)(fb + 8 * it);
        #pragma unroll
        for (int it = 0; it < 17; it++) {
            const int p = c4 + 4 * it;          // 0..67
            *(uint32_t*)(AH + r * K1PAD + 2 * p) = pack_hi(v[it].x, v[it].y);
            *(uint32_t*)(AL + r * K1PAD + 2 * p) = pack_lo(v[it].x, v[it].y);
        }
        // zero pad k = 136..151 (pairs 68..75)
        *(uint32_t*)(AH + r * K1PAD + 2 * (68 + c4)) = 0;
        *(uint32_t*)(AL + r * K1PAD + 2 * (68 + c4)) = 0;
        *(uint32_t*)(AH + r * K1PAD + 2 * (72 + c4)) = 0;
        *(uint32_t*)(AL + r * K1PAD + 2 * (72 + c4)) = 0;
    }
    CP_WAIT0();
    __syncthreads();

    float acc[8][4];
    #pragma unroll
    for (int t = 0; t < 8; t++)
        #pragma unroll
        for (int q = 0; q < 4; q++) acc[t][q] = 0.f;

    // ---- layer 1: 9 ksteps, stride K1PAD, 2-term (Ah+Al)·W ----
    #pragma unroll
    for (int ks = 0; ks < 9; ks++) {
        const int k0 = ks * 16;
        uint32_t ah[4], al[4];
        ldsm_x4(ah, uAH + (a_row * K1PAD + k0 + a_kof) * 2);
        ldsm_x4(al, uAL + (a_row * K1PAD + k0 + a_kof) * 2);
        #pragma unroll
        for (int np = 0; np < 4; np++) {
            const int n0 = nside + np * 16;
            uint32_t wh[4];
            ldsm_x4(wh, uW1 + ((n0 + w_rof) * K1PAD + k0 + w_kof) * 2);
            mma16816(acc[2*np],   ah, wh[0], wh[1]);
            mma16816(acc[2*np],   al, wh[0], wh[1]);
            mma16816(acc[2*np+1], ah, wh[2], wh[3]);
            mma16816(acc[2*np+1], al, wh[2], wh[3]);
        }
    }
    __syncthreads();    // all layer-1 A reads complete before h1 overwrite

    // ---- epilogue 1: relu(+b1) -> hi/lo fp16 into A buffers, stride K2PAD ----
    {
        const int rA = m0 + (lane >> 2);
        #pragma unroll
        for (int nt = 0; nt < 8; nt++) {
            const int c = nside + nt * 8 + (lane & 3) * 2;
            float v0 = fmaxf(acc[nt][0] + sB1[c],     0.f);
            float v1 = fmaxf(acc[nt][1] + sB1[c + 1], 0.f);
            float v2 = fmaxf(acc[nt][2] + sB1[c],     0.f);
            float v3 = fmaxf(acc[nt][3] + sB1[c + 1], 0.f);
            *(uint32_t*)(AH + rA * K2PAD + c)       = pack_hi(v0, v1);
            *(uint32_t*)(AL + rA * K2PAD + c)       = pack_lo(v0, v1);
            *(uint32_t*)(AH + (rA + 8) * K2PAD + c) = pack_hi(v2, v3);
            *(uint32_t*)(AL + (rA + 8) * K2PAD + c) = pack_lo(v2, v3);
        }
    }
    __syncthreads();

    #pragma unroll
    for (int t = 0; t < 8; t++)
        #pragma unroll
        for (int q = 0; q < 4; q++) acc[t][q] = 0.f;

    // ---- layer 2: 8 ksteps, stride K2PAD ----
    #pragma unroll
    for (int ks = 0; ks < 8; ks++) {
        const int k0 = ks * 16;
        uint32_t ah[4], al[4];
        ldsm_x4(ah, uAH + (a_row * K2PAD + k0 + a_kof) * 2);
        ldsm_x4(al, uAL + (a_row * K2PAD + k0 + a_kof) * 2);
        #pragma unroll
        for (int np = 0; np < 4; np++) {
            const int n0 = nside + np * 16;
            uint32_t wh[4];
            ldsm_x4(wh, uW2 + ((n0 + w_rof) * K2PAD + k0 + w_kof) * 2);
            mma16816(acc[2*np],   ah, wh[0], wh[1]);
            mma16816(acc[2*np],   al, wh[0], wh[1]);
            mma16816(acc[2*np+1], ah, wh[2], wh[3]);
            mma16816(acc[2*np+1], al, wh[2], wh[3]);
        }
    }

    // ---- epilogue 2: relu(+b2) . W3, reduce to scores ----
    {
        float pl = 0.f, ph = 0.f;
        #pragma unroll
        for (int nt = 0; nt < 8; nt++) {
            const int c = nside + nt * 8 + (lane & 3) * 2;
            pl = fmaf(fmaxf(acc[nt][0] + sB2[c],     0.f), sW3[c],     pl);
            pl = fmaf(fmaxf(acc[nt][1] + sB2[c + 1], 0.f), sW3[c + 1], pl);
            ph = fmaf(fmaxf(acc[nt][2] + sB2[c],     0.f), sW3[c],     ph);
            ph = fmaf(fmaxf(acc[nt][3] + sB2[c + 1], 0.f), sW3[c + 1], ph);
        }
        pl += __shfl_xor_sync(0xFFFFFFFF, pl, 1);
        pl += __shfl_xor_sync(0xFFFFFFFF, pl, 2);
        ph += __shfl_xor_sync(0xFFFFFFFF, ph, 1);
        ph += __shfl_xor_sync(0xFFFFFFFF, ph, 2);
        if ((lane & 3) == 0) {
            const int r = m0 + (lane >> 2);
            red[r * 2 + (wid & 1)]       = pl;
            red[(r + 8) * 2 + (wid & 1)] = ph;
        }
    }
    __syncthreads();
    if (tid < 128)
        g_scores[row0 + tid] = red[tid * 2] + red[tid * 2 + 1] + __ldg(b3);
}

// ---------------- pairwise lambda kernel: 2 blocks per batch ----------------
__global__ __launch_bounds__(128, 8)
void lambda_kernel(const int* __restrict__ labels, float* __restrict__ out)
{
    __shared__ float4 elg[NN];     // {exp(s), 1+log2(1+s), 2^label, 0}

    const int bid   = blockIdx.x;
    const int batch = bid >> 1;
    const int half  = bid & 1;
    const int tid   = threadIdx.x;

    for (int j = tid; j < NN; j += 128) {
        float s = g_scores[batch * NN + j];
        int   l = labels[batch * NN + j];
        elg[j] = make_float4(expf(s), 1.0f + log2f(1.0f + s), exp2f((float)l), 0.f);
    }
    __syncthreads();

    const int i = half * 128 + tid;
    const float4 me = elg[i];
    const float ei = me.x, Mi = me.y, gi = me.z;

    float acc = 0.f;
    #pragma unroll 8
    for (int j = 0; j < NN; j++) {
        float4 v  = elg[j];
        float sg  = gi - v.z;
        float t   = (sg > 0.f) ? ei : v.x;
        float num = sg * t;
        float den = fabsf(fmaxf(Mi, v.y)) * (ei + v.x);
        acc += __fdividef(num, den);
    }
    out[batch * NN + i] = 0.5f * acc;
}

extern "C" void kernel_launch(void* const* d_in, const int* in_sizes, int n_in,
                              void* d_out, int out_size)
{
    const float* feat   = (const float*)d_in[0];
    const int*   labels = (const int*)d_in[1];
    const float* W1 = (const float*)d_in[2];
    const float* b1 = (const float*)d_in[3];
    const float* W2 = (const float*)d_in[4];
    const float* b2 = (const float*)d_in[5];
    const float* W3 = (const float*)d_in[6];
    const float* b3 = (const float*)d_in[7];
    float* out = (float*)d_out;

    static bool attr_set = false;
    if (!attr_set) {
        cudaFuncSetAttribute(mlp_mma, cudaFuncAttributeMaxDynamicSharedMemorySize,
                             (int)SMEM_BYTES);
        attr_set = true;
    }

    prep_w<<<(HH * K1PAD + HH * 128 + 255) / 256, 256>>>(W1, W2);
    mlp_mma<<<ROWS / 128, NT, SMEM_BYTES>>>(feat, b1, b2, W3, b3);
    lambda_kernel<<<2 * BB, 128>>>(labels, out);
}

// round 8
// speedup vs baseline: 3.3547x; 1.2472x over previous
#include <cuda_runtime.h>
#include <cuda_fp16.h>
#include <math.h>
#include <stdint.h>

#define BB 256
#define NN 256
#define DD 136
#define HH 128
#define ROWS (BB*NN)

#define K1PAD 152      // layer-1 K stride (304B rows -> conflict-free ldmatrix)
#define K2PAD 136      // layer-2 K stride (272B rows -> conflict-free)
#define NT    512      // 16 warps

// ---------------- scratch globals ----------------
__device__ float g_scores[ROWS];
__device__ __align__(16) __half g_W1t[HH * K1PAD];   // fp16, transposed [n][k], zero-padded
__device__ __align__(16) __half g_W2t[HH * K2PAD];

// ---------------- smem layout ----------------
#define A_BYTES  (128 * K1PAD * 2)          // 38912
#define W1_BYTES (128 * K1PAD * 2)          // 38912
#define W2_BYTES (128 * K2PAD * 2)          // 34816
#define OFF_A    0
#define OFF_W1   (A_BYTES)                  // 38912
#define OFF_W2   (OFF_W1 + W1_BYTES)        // 77824
#define OFF_B1   (OFF_W2 + W2_BYTES)        // 112640
#define OFF_B2   (OFF_B1 + 512)
#define OFF_W3   (OFF_B2 + 512)
#define OFF_RED  (OFF_W3 + 512)
#define SMEM_BYTES (OFF_RED + 1024)         // 115200

__device__ __forceinline__ uint32_t smem_u32(const void* p) {
    uint32_t a;
    asm("{ .reg .u64 t; cvta.to.shared.u64 t, %1; cvt.u32.u64 %0, t; }" : "=r"(a) : "l"(p));
    return a;
}
__device__ __forceinline__ void cp_async16(uint32_t dst, const void* src) {
    asm volatile("cp.async.cg.shared.global [%0], [%1], 16;" :: "r"(dst), "l"(src));
}
#define CP_COMMIT() asm volatile("cp.async.commit_group;" ::: "memory")
#define CP_WAIT0()  asm volatile("cp.async.wait_group 0;" ::: "memory")

__device__ __forceinline__ void ldsm_x4(uint32_t* r, uint32_t addr) {
    asm volatile("ldmatrix.sync.aligned.m8n8.x4.shared.b16 {%0,%1,%2,%3}, [%4];"
        : "=r"(r[0]), "=r"(r[1]), "=r"(r[2]), "=r"(r[3]) : "r"(addr));
}
__device__ __forceinline__ void mma16816(float* d, const uint32_t* a, uint32_t b0, uint32_t b1) {
    asm volatile("mma.sync.aligned.m16n8k16.row.col.f32.f16.f16.f32 "
        "{%0,%1,%2,%3}, {%4,%5,%6,%7}, {%8,%9}, {%0,%1,%2,%3};"
        : "+f"(d[0]), "+f"(d[1]), "+f"(d[2]), "+f"(d[3])
        : "r"(a[0]), "r"(a[1]), "r"(a[2]), "r"(a[3]), "r"(b0), "r"(b1));
}
__device__ __forceinline__ uint32_t pack_h2(float x, float y) {
    __half h0 = __float2half_rn(x), h1 = __float2half_rn(y);
    return ((uint32_t)__half_as_ushort(h1) << 16) | __half_as_ushort(h0);
}

// ---------------- weight prep: fp16 round + transpose to [n][k] ----------------
__global__ void prep_w(const float* __restrict__ W1, const float* __restrict__ W2) {
    int idx = blockIdx.x * 256 + threadIdx.x;
    if (idx < HH * K1PAD) {
        int n = idx & 127, k = idx >> 7;
        float v = (k < DD) ? W1[k * HH + n] : 0.f;
        g_W1t[n * K1PAD + k] = __float2half_rn(v);
        return;
    }
    int idx2 = idx - HH * K1PAD;
    if (idx2 < HH * 128) {
        int n = idx2 & 127, k = idx2 >> 7;
        g_W2t[n * K2PAD + k] = __float2half_rn(W2[k * HH + n]);
    }
}

// ---------------- fused MLP, warp-level fp16 MMA (single-term) ----------------
__global__ __launch_bounds__(NT, 1)
void mlp_mma(const float* __restrict__ feat,
             const float* __restrict__ b1, const float* __restrict__ b2,
             const float* __restrict__ W3, const float* __restrict__ b3)
{
    extern __shared__ char smem[];
    __half* A  = (__half*)(smem + OFF_A);
    float* sB1 = (float*)(smem + OFF_B1);
    float* sB2 = (float*)(smem + OFF_B2);
    float* sW3 = (float*)(smem + OFF_W3);
    float* red = (float*)(smem + OFF_RED);

    const int tid  = threadIdx.x;
    const int lane = tid & 31;
    const int wid  = tid >> 5;
    const int m0    = (wid >> 1) * 16;
    const int nside = (wid & 1) * 64;
    const long row0 = (long)blockIdx.x * 128;

    const uint32_t uA  = smem_u32(smem + OFF_A);
    const uint32_t uW1 = smem_u32(smem + OFF_W1);
    const uint32_t uW2 = smem_u32(smem + OFF_W2);

    // ldmatrix address components
    const int a_row = m0 + (lane & 7) + ((lane >> 3) & 1) * 8;
    const int a_kof = (lane >> 4) * 8;
    const int w_rof = (lane & 7) + (lane >> 4) * 8;
    const int w_kof = ((lane >> 3) & 1) * 8;

    // ---- stage 1: weight tiles via cp.async ----
    {
        const char* s;
        s = (const char*)g_W1t;
        for (int i = tid; i < W1_BYTES / 16; i += NT) cp_async16(uW1 + i * 16, s + i * 16);
        s = (const char*)g_W2t;
        for (int i = tid; i < W2_BYTES / 16; i += NT) cp_async16(uW2 + i * 16, s + i * 16);
        CP_COMMIT();
    }

    // ---- stage 2: biases / W3 ----
    if (tid < 128) { sB1[tid] = b1[tid]; sB2[tid] = b2[tid]; sW3[tid] = W3[tid]; }

    // ---- stage 3: features -> fp16 ----
    {
        const int r  = tid >> 2;        // row 0..127
        const int c4 = tid & 3;         // pair-lane
        const float* fb = feat + row0 * DD + (long)r * DD + 2 * c4;
        float2 v[17];
        #pragma unroll
        for (int it = 0; it < 17; it++) v[it] = *(const float2*)(fb + 8 * it);
        #pragma unroll
        for (int it = 0; it < 17; it++) {
            const int p = c4 + 4 * it;          // 0..67
            *(uint32_t*)(A + r * K1PAD + 2 * p) = pack_h2(v[it].x, v[it].y);
        }
        // zero pad k = 136..151 (pairs 68..75)
        *(uint32_t*)(A + r * K1PAD + 2 * (68 + c4)) = 0;
        *(uint32_t*)(A + r * K1PAD + 2 * (72 + c4)) = 0;
    }
    CP_WAIT0();
    __syncthreads();

    float acc[8][4];
    #pragma unroll
    for (int t = 0; t < 8; t++)
        #pragma unroll
        for (int q = 0; q < 4; q++) acc[t][q] = 0.f;

    // ---- layer 1: 9 ksteps ----
    #pragma unroll
    for (int ks = 0; ks < 9; ks++) {
        const int k0 = ks * 16;
        uint32_t a[4];
        ldsm_x4(a, uA + (a_row * K1PAD + k0 + a_kof) * 2);
        #pragma unroll
        for (int np = 0; np < 4; np++) {
            const int n0 = nside + np * 16;
            uint32_t w[4];
            ldsm_x4(w, uW1 + ((n0 + w_rof) * K1PAD + k0 + w_kof) * 2);
            mma16816(acc[2*np],   a, w[0], w[1]);
            mma16816(acc[2*np+1], a, w[2], w[3]);
        }
    }
    __syncthreads();

    // ---- epilogue 1: relu(+b1) -> fp16 into A, stride K2PAD ----
    {
        const int rA = m0 + (lane >> 2);
        #pragma unroll
        for (int nt = 0; nt < 8; nt++) {
            const int c = nside + nt * 8 + (lane & 3) * 2;
            float v0 = fmaxf(acc[nt][0] + sB1[c],     0.f);
            float v1 = fmaxf(acc[nt][1] + sB1[c + 1], 0.f);
            float v2 = fmaxf(acc[nt][2] + sB1[c],     0.f);
            float v3 = fmaxf(acc[nt][3] + sB1[c + 1], 0.f);
            *(uint32_t*)(A + rA * K2PAD + c)       = pack_h2(v0, v1);
            *(uint32_t*)(A + (rA + 8) * K2PAD + c) = pack_h2(v2, v3);
        }
    }
    __syncthreads();

    #pragma unroll
    for (int t = 0; t < 8; t++)
        #pragma unroll
        for (int q = 0; q < 4; q++) acc[t][q] = 0.f;

    // ---- layer 2: 8 ksteps ----
    #pragma unroll
    for (int ks = 0; ks < 8; ks++) {
        const int k0 = ks * 16;
        uint32_t a[4];
        ldsm_x4(a, uA + (a_row * K2PAD + k0 + a_kof) * 2);
        #pragma unroll
        for (int np = 0; np < 4; np++) {
            const int n0 = nside + np * 16;
            uint32_t w[4];
            ldsm_x4(w, uW2 + ((n0 + w_rof) * K2PAD + k0 + w_kof) * 2);
            mma16816(acc[2*np],   a, w[0], w[1]);
            mma16816(acc[2*np+1], a, w[2], w[3]);
        }
    }

    // ---- epilogue 2: relu(+b2) . W3, reduce to scores ----
    {
        float pl = 0.f, ph = 0.f;
        #pragma unroll
        for (int nt = 0; nt < 8; nt++) {
            const int c = nside + nt * 8 + (lane & 3) * 2;
            pl = fmaf(fmaxf(acc[nt][0] + sB2[c],     0.f), sW3[c],     pl);
            pl = fmaf(fmaxf(acc[nt][1] + sB2[c + 1], 0.f), sW3[c + 1], pl);
            ph = fmaf(fmaxf(acc[nt][2] + sB2[c],     0.f), sW3[c],     ph);
            ph = fmaf(fmaxf(acc[nt][3] + sB2[c + 1], 0.f), sW3[c + 1], ph);
        }
        pl += __shfl_xor_sync(0xFFFFFFFF, pl, 1);
        pl += __shfl_xor_sync(0xFFFFFFFF, pl, 2);
        ph += __shfl_xor_sync(0xFFFFFFFF, ph, 1);
        ph += __shfl_xor_sync(0xFFFFFFFF, ph, 2);
        if ((lane & 3) == 0) {
            const int r = m0 + (lane >> 2);
            red[r * 2 + (wid & 1)]       = pl;
            red[(r + 8) * 2 + (wid & 1)] = ph;
        }
    }
    __syncthreads();
    if (tid < 128)
        g_scores[row0 + tid] = red[tid * 2] + red[tid * 2 + 1] + __ldg(b3);
}

// ---------------- lambda kernel: 2 blocks/batch, j-loop split 2 ways ----------------
__global__ __launch_bounds__(256, 8)
void lambda_kernel(const int* __restrict__ labels, float* __restrict__ out)
{
    __shared__ float4 elg[NN];       // {exp(s), 1+log2(1+s), 2^label, 0}
    __shared__ float  part[128];     // partial sums from j-half 0

    const int bid   = blockIdx.x;        // 0..511
    const int batch = bid >> 1;
    const int ihalf = bid & 1;
    const int tid   = threadIdx.x;       // 0..255
    const int il    = tid & 127;         // i within half
    const int jh    = tid >> 7;          // j-half 0/1

    {
        float s = g_scores[batch * NN + tid];
        int   l = labels[batch * NN + tid];
        elg[tid] = make_float4(expf(s), 1.0f + log2f(1.0f + s), exp2f((float)l), 0.f);
    }
    __syncthreads();

    const int i = ihalf * 128 + il;
    const float4 me = elg[i];
    const float ei = me.x, Mi = me.y, gi = me.z;

    float acc0 = 0.f, acc1 = 0.f;
    const int j0 = jh * 128;
    #pragma unroll 4
    for (int j = 0; j < 128; j += 2) {
        float4 va = elg[j0 + j];
        float4 vb = elg[j0 + j + 1];
        float sga = gi - va.z;
        float sgb = gi - vb.z;
        float ta = (sga > 0.f) ? ei : va.x;
        float tb = (sgb > 0.f) ? ei : vb.x;
        acc0 += __fdividef(sga * ta, fabsf(fmaxf(Mi, va.y)) * (ei + va.x));
        acc1 += __fdividef(sgb * tb, fabsf(fmaxf(Mi, vb.y)) * (ei + vb.x));
    }
    float acc = acc0 + acc1;
    if (jh == 0) part[il] = acc;
    __syncthreads();
    if (jh == 1)
        out[batch * NN + i] = 0.5f * (acc + part[il]);
}

extern "C" void kernel_launch(void* const* d_in, const int* in_sizes, int n_in,
                              void* d_out, int out_size)
{
    const float* feat   = (const float*)d_in[0];
    const int*   labels = (const int*)d_in[1];
    const float* W1 = (const float*)d_in[2];
    const float* b1 = (const float*)d_in[3];
    const float* W2 = (const float*)d_in[4];
    const float* b2 = (const float*)d_in[5];
    const float* W3 = (const float*)d_in[6];
    const float* b3 = (const float*)d_in[7];
    float* out = (float*)d_out;

    static bool attr_set = false;
    if (!attr_set) {
        cudaFuncSetAttribute(mlp_mma, cudaFuncAttributeMaxDynamicSharedMemorySize,
                             (int)SMEM_BYTES);
        attr_set = true;
    }

    prep_w<<<(HH * K1PAD + HH * 128 + 255) / 256, 256>>>(W1, W2);
    mlp_mma<<<ROWS / 128, NT, SMEM_BYTES>>>(feat, b1, b2, W3, b3);
    lambda_kernel<<<2 * BB, 256>>>(labels, out);
}